// round 1
// baseline (speedup 1.0000x reference)
#include <cuda_runtime.h>
#include <math.h>

namespace {
constexpr int NB = 4, TE = 256, TD = 512, DM = 512, DI = 1024, DS = 16, DTR = 32, NM = 80;
constexpr int ME = NB * TE;   // 1024 encoder rows
constexpr int MD = NB * TD;   // 2048 decoder rows
}

// ---------------- scratch (device globals; no allocation allowed) ----------------
__device__ float g_x0[MD * DM];
__device__ float g_x1[MD * DM];
__device__ float g_xz[MD * 2 * DI];
__device__ float g_u[MD * DI];
__device__ float g_xdbl[MD * 64];
__device__ float g_delta[MD * DI];
__device__ float g_gate[MD * DI];
__device__ float g_im2col[ME * DM * 3];
__device__ float g_wt[DM * 3 * DM];
__device__ float g_h1[ME * DM];
__device__ float g_h2[ME * DM];
__device__ float g_dur[ME];
__device__ int   g_idx[NB * TD];
__device__ float g_mask[NB * TD];

__device__ __forceinline__ float softplus_f(float x) {
    return x > 0.f ? x + log1pf(expf(-x)) : log1pf(expf(x));
}
__device__ __forceinline__ float silu_f(float x) {
    return x / (1.f + expf(-x));
}

// ---------------- embedding ----------------
__global__ void embed_k(const int* __restrict__ text, const float* __restrict__ emb,
                        float* __restrict__ out) {
    int i = blockIdx.x * blockDim.x + threadIdx.x;
    if (i >= ME * DM) return;
    int c = i % DM;
    int r = i / DM;
    out[i] = emb[text[r] * DM + c];
}

// ---------------- generic tiled fp32 GEMM with fused epilogues ----------------
// EPI: 0=none, 1=softplus(acc+bias), 2=relu(acc+bias)*bn_scale+bn_shift, 3=acc*rowmask[m]
template<int EPI>
__global__ __launch_bounds__(256) void sgemm_k(
    const float* __restrict__ A, const float* __restrict__ W, float* __restrict__ C,
    int M, int N, int K, int lda, int ldb, int ldc,
    const float* __restrict__ bias, const float* __restrict__ gamma,
    const float* __restrict__ beta, const float* __restrict__ rmask)
{
    __shared__ float As[16][64];
    __shared__ float Bs[16][64];
    const int bm = blockIdx.y * 64, bn = blockIdx.x * 64;
    const int tid = threadIdx.x;
    const int tx = tid & 15, ty = tid >> 4;
    const int am = tid >> 2, ak = (tid & 3) << 2;   // A tile load mapping
    const int bk = tid >> 4, bn4 = (tid & 15) << 2; // B tile load mapping
    float acc[4][4] = {};
    for (int k0 = 0; k0 < K; k0 += 16) {
        float4 av = make_float4(0.f, 0.f, 0.f, 0.f);
        if (bm + am < M)
            av = *reinterpret_cast<const float4*>(A + (size_t)(bm + am) * lda + k0 + ak);
        As[ak + 0][am] = av.x; As[ak + 1][am] = av.y;
        As[ak + 2][am] = av.z; As[ak + 3][am] = av.w;
        float4 bv;
        if (bn + bn4 + 3 < N) {
            bv = *reinterpret_cast<const float4*>(W + (size_t)(k0 + bk) * ldb + bn + bn4);
        } else {
            const float* wr = W + (size_t)(k0 + bk) * ldb;
            bv.x = (bn + bn4 + 0 < N) ? wr[bn + bn4 + 0] : 0.f;
            bv.y = (bn + bn4 + 1 < N) ? wr[bn + bn4 + 1] : 0.f;
            bv.z = (bn + bn4 + 2 < N) ? wr[bn + bn4 + 2] : 0.f;
            bv.w = (bn + bn4 + 3 < N) ? wr[bn + bn4 + 3] : 0.f;
        }
        Bs[bk][bn4 + 0] = bv.x; Bs[bk][bn4 + 1] = bv.y;
        Bs[bk][bn4 + 2] = bv.z; Bs[bk][bn4 + 3] = bv.w;
        __syncthreads();
        #pragma unroll
        for (int kk = 0; kk < 16; kk++) {
            float4 a4 = *reinterpret_cast<const float4*>(&As[kk][ty << 2]);
            float4 b4 = *reinterpret_cast<const float4*>(&Bs[kk][tx << 2]);
            float af[4] = {a4.x, a4.y, a4.z, a4.w};
            float bf[4] = {b4.x, b4.y, b4.z, b4.w};
            #pragma unroll
            for (int i = 0; i < 4; i++)
                #pragma unroll
                for (int j = 0; j < 4; j++)
                    acc[i][j] = fmaf(af[i], bf[j], acc[i][j]);
        }
        __syncthreads();
    }
    #pragma unroll
    for (int i = 0; i < 4; i++) {
        int m = bm + (ty << 2) + i;
        if (m >= M) continue;
        #pragma unroll
        for (int j = 0; j < 4; j++) {
            int n = bn + (tx << 2) + j;
            if (n >= N) continue;
            float v = acc[i][j];
            if (EPI == 1) v = softplus_f(v + bias[n]);
            else if (EPI == 2) v = fmaxf(v + bias[n], 0.f) * (gamma[n] * rsqrtf(1.f + 1e-5f)) + beta[n];
            else if (EPI == 3) v *= rmask[m];
            C[(size_t)m * ldc + n] = v;
        }
    }
}

// ---------------- depthwise causal conv (K=4) + SiLU ----------------
__global__ void dwconv_silu_k(const float* __restrict__ xz, const float* __restrict__ w,
                              const float* __restrict__ bcv, float* __restrict__ u, int L) {
    int i = blockIdx.x * blockDim.x + threadIdx.x;
    int total = NB * L * DI;
    if (i >= total) return;
    int d = i % DI;
    int bt = i / DI;
    int t = bt % L;
    int bb = bt / L;
    float acc = bcv[d];
    const float* wr = w + d * 4;
    #pragma unroll
    for (int k = 0; k < 4; k++) {
        int ts = t - 3 + k;
        if (ts >= 0)
            acc = fmaf(wr[k], xz[((size_t)(bb * L + ts)) * 2048 + d], acc);
    }
    u[i] = silu_f(acc);
}

// ---------------- selective scan: 4 threads per (b,d), 4 states each ----------------
__global__ void scan_k(const float* __restrict__ xdbl, const float* __restrict__ delta,
                       const float* __restrict__ u, const float* __restrict__ xz,
                       const float* __restrict__ Alog, const float* __restrict__ Dp,
                       float* __restrict__ gate, int L) {
    int gt = blockIdx.x * blockDim.x + threadIdx.x;
    if (gt >= NB * DI * 4) return;
    int lane = gt & 3;
    int gid = gt >> 2;
    int d = gid % DI;
    int bb = gid / DI;
    float a0 = -expf(Alog[d * DS + lane * 4 + 0]);
    float a1 = -expf(Alog[d * DS + lane * 4 + 1]);
    float a2 = -expf(Alog[d * DS + lane * 4 + 2]);
    float a3 = -expf(Alog[d * DS + lane * 4 + 3]);
    float Dd = Dp[d];
    float h0 = 0.f, h1 = 0.f, h2 = 0.f, h3 = 0.f;
    for (int t = 0; t < L; t++) {
        size_t row = (size_t)bb * L + t;
        float dl = delta[row * DI + d];
        float ut = u[row * DI + d];
        float du = dl * ut;
        const float* xd = xdbl + row * 64;
        float4 Bv = *reinterpret_cast<const float4*>(xd + 32 + lane * 4);
        float4 Cv = *reinterpret_cast<const float4*>(xd + 48 + lane * 4);
        h0 = fmaf(__expf(dl * a0), h0, du * Bv.x);
        h1 = fmaf(__expf(dl * a1), h1, du * Bv.y);
        h2 = fmaf(__expf(dl * a2), h2, du * Bv.z);
        h3 = fmaf(__expf(dl * a3), h3, du * Bv.w);
        float y = h0 * Cv.x + h1 * Cv.y + h2 * Cv.z + h3 * Cv.w;
        y += __shfl_xor_sync(0xffffffffu, y, 1);
        y += __shfl_xor_sync(0xffffffffu, y, 2);
        if (lane == 0) {
            float res = xz[row * 2048 + 1024 + d];
            gate[row * DI + d] = (y + ut * Dd) * silu_f(res);
        }
    }
}

// ---------------- duration predictor helpers ----------------
// w [O=512][C=512][K=3] -> wt [(k*512+c)][d]
__global__ void wt_k(const float* __restrict__ w, float* __restrict__ wt) {
    int i = blockIdx.x * blockDim.x + threadIdx.x;
    if (i >= DM * DM * 3) return;
    int k = i % 3;
    int c = (i / 3) % DM;
    int d = i / (3 * DM);
    wt[(size_t)(k * DM + c) * DM + d] = w[i];
}
// src [b*256+t][512] -> dst [b*256+t][k*512+c], pad=1
__global__ void im2col_k(const float* __restrict__ src, float* __restrict__ dst) {
    int i = blockIdx.x * blockDim.x + threadIdx.x;
    if (i >= ME * DM * 3) return;
    int c = i % DM;
    int k = (i / DM) % 3;
    int r = i / (DM * 3);
    int t = r % TE;
    int ts = t - 1 + k;
    float v = 0.f;
    if (ts >= 0 && ts < TE) v = src[(size_t)(r - t + ts) * DM + c];
    dst[i] = v;
}
// 1x1 conv to 1 channel + softplus: one warp per (b,t)
__global__ void dur_k(const float* __restrict__ h2, const float* __restrict__ w3,
                      const float* __restrict__ b3, float* __restrict__ dur) {
    int warp = (blockIdx.x * blockDim.x + threadIdx.x) >> 5;
    int lane = threadIdx.x & 31;
    if (warp >= ME) return;
    const float* hr = h2 + (size_t)warp * DM;
    float s = 0.f;
    for (int c = lane; c < DM; c += 32) s = fmaf(hr[c], w3[c], s);
    #pragma unroll
    for (int o = 16; o; o >>= 1) s += __shfl_xor_sync(0xffffffffu, s, o);
    if (lane == 0) dur[warp] = softplus_f(s + b3[0]);
}

// ---------------- length regulator ----------------
__global__ void expand_k(const float* __restrict__ dur, int* __restrict__ idx,
                         float* __restrict__ mask) {
    __shared__ float ends[TE];
    int bb = blockIdx.x;
    int t = threadIdx.x;
    ends[t] = rintf(fmaxf(dur[bb * TE + t], 0.f));   // round-half-to-even matches jnp.round
    __syncthreads();
    if (t == 0) {
        float s = 0.f;
        for (int i = 0; i < TE; i++) { s += ends[i]; ends[i] = s; }
    }
    __syncthreads();
    float total = ends[TE - 1];
    for (int tp = t; tp < TD; tp += TE) {
        float fp = (float)tp;
        int lo = 0, hi = TE;
        while (lo < hi) { int mid = (lo + hi) >> 1; if (ends[mid] <= fp) lo = mid + 1; else hi = mid; }
        int id = lo < TE - 1 ? lo : TE - 1;
        idx[bb * TD + tp] = id;
        mask[bb * TD + tp] = fp < total ? 1.f : 0.f;
    }
}
__global__ void gather_k(const float* __restrict__ enc, const int* __restrict__ idx,
                         const float* __restrict__ mask, float* __restrict__ out) {
    int i = blockIdx.x * blockDim.x + threadIdx.x;
    if (i >= MD * DM) return;
    int c = i % DM;
    int r = i / DM;        // b*512 + t
    int bb = r / TD;
    out[i] = enc[(size_t)(bb * TE + idx[r]) * DM + c] * mask[r];
}

// ---------------- rmsnorm ----------------
__global__ void rmsnorm_k(const float* __restrict__ x, const float* __restrict__ g,
                          float* __restrict__ out) {
    int r = blockIdx.x;
    const float* xr = x + (size_t)r * DM;
    float s = 0.f;
    for (int c = threadIdx.x; c < DM; c += blockDim.x) { float v = xr[c]; s = fmaf(v, v, s); }
    __shared__ float red[4];
    #pragma unroll
    for (int o = 16; o; o >>= 1) s += __shfl_xor_sync(0xffffffffu, s, o);
    int w = threadIdx.x >> 5;
    if ((threadIdx.x & 31) == 0) red[w] = s;
    __syncthreads();
    if (threadIdx.x == 0) red[0] = red[0] + red[1] + red[2] + red[3];
    __syncthreads();
    float scale = rsqrtf(red[0] / (float)DM + 1e-6f);
    for (int c = threadIdx.x; c < DM; c += blockDim.x)
        out[(size_t)r * DM + c] = xr[c] * scale * g[c];
}

__global__ void tail_k(float* __restrict__ out, const float* __restrict__ mask, int n) {
    int i = blockIdx.x * blockDim.x + threadIdx.x;
    if (i >= n) return;
    out[i] = (i < NB * TD) ? mask[i] : 0.f;
}

// ---------------- host driver ----------------
static void launch_gemm(int epi, const float* A, const float* W, float* C,
                        int M, int N, int K, int lda, int ldb, int ldc,
                        const float* bias = nullptr, const float* gamma = nullptr,
                        const float* beta = nullptr, const float* rmask = nullptr) {
    dim3 grid((N + 63) / 64, (M + 63) / 64);
    if (epi == 0)      sgemm_k<0><<<grid, 256>>>(A, W, C, M, N, K, lda, ldb, ldc, bias, gamma, beta, rmask);
    else if (epi == 1) sgemm_k<1><<<grid, 256>>>(A, W, C, M, N, K, lda, ldb, ldc, bias, gamma, beta, rmask);
    else if (epi == 2) sgemm_k<2><<<grid, 256>>>(A, W, C, M, N, K, lda, ldb, ldc, bias, gamma, beta, rmask);
    else               sgemm_k<3><<<grid, 256>>>(A, W, C, M, N, K, lda, ldb, ldc, bias, gamma, beta, rmask);
}

extern "C" void kernel_launch(void* const* d_in, const int* in_sizes, int n_in,
                              void* d_out, int out_size) {
    (void)n_in;
    // Runtime detection of input ordering:
    //  reference-signature order: in_sizes[2] == 3*512*2048 (enc_in_w)
    //  setup_inputs dict order:   in_sizes[2] == 512*512*3  (dp_c1_w)
    int map[32];
    if (in_sizes[2] == 3 * DM * 2 * DI) {
        for (int i = 0; i < 32; i++) map[i] = i;
    } else {
        const int m[32] = {0, 1,
                           14, 15, 16, 17, 18, 19, 20, 21, 22,   // enc_*
                           2, 3, 4, 5, 6, 7, 8, 9, 10, 11,       // dp_*
                           23, 24, 25, 26, 27, 28, 29, 30, 31,   // dec_*
                           12, 13};                              // norm_g, out_w
        for (int i = 0; i < 32; i++) map[i] = m[i];
    }
    const int*   text      = (const int*)  d_in[map[0]];
    const float* emb       = (const float*)d_in[map[1]];
    const float* enc_in_w  = (const float*)d_in[map[2]];
    const float* enc_cw    = (const float*)d_in[map[3]];
    const float* enc_cb    = (const float*)d_in[map[4]];
    const float* enc_xpw   = (const float*)d_in[map[5]];
    const float* enc_dtw   = (const float*)d_in[map[6]];
    const float* enc_dtb   = (const float*)d_in[map[7]];
    const float* enc_alog  = (const float*)d_in[map[8]];
    const float* enc_dp    = (const float*)d_in[map[9]];
    const float* enc_ow    = (const float*)d_in[map[10]];
    const float* dp_c1w    = (const float*)d_in[map[11]];
    const float* dp_c1b    = (const float*)d_in[map[12]];
    const float* dp_g1     = (const float*)d_in[map[13]];
    const float* dp_b1     = (const float*)d_in[map[14]];
    const float* dp_c2w    = (const float*)d_in[map[15]];
    const float* dp_c2b    = (const float*)d_in[map[16]];
    const float* dp_g2     = (const float*)d_in[map[17]];
    const float* dp_b2     = (const float*)d_in[map[18]];
    const float* dp_c3w    = (const float*)d_in[map[19]];
    const float* dp_c3b    = (const float*)d_in[map[20]];
    const float* dec_in_w  = (const float*)d_in[map[21]];
    const float* dec_cw    = (const float*)d_in[map[22]];
    const float* dec_cb    = (const float*)d_in[map[23]];
    const float* dec_xpw   = (const float*)d_in[map[24]];
    const float* dec_dtw   = (const float*)d_in[map[25]];
    const float* dec_dtb   = (const float*)d_in[map[26]];
    const float* dec_alog  = (const float*)d_in[map[27]];
    const float* dec_dpv   = (const float*)d_in[map[28]];
    const float* dec_ow    = (const float*)d_in[map[29]];
    const float* norm_g    = (const float*)d_in[map[30]];
    const float* out_w     = (const float*)d_in[map[31]];

    float *x0, *x1, *xz, *u, *xdbl, *delta, *gate, *im, *wt, *h1, *h2, *dur, *mask;
    int* idx;
    cudaGetSymbolAddress((void**)&x0,   g_x0);
    cudaGetSymbolAddress((void**)&x1,   g_x1);
    cudaGetSymbolAddress((void**)&xz,   g_xz);
    cudaGetSymbolAddress((void**)&u,    g_u);
    cudaGetSymbolAddress((void**)&xdbl, g_xdbl);
    cudaGetSymbolAddress((void**)&delta,g_delta);
    cudaGetSymbolAddress((void**)&gate, g_gate);
    cudaGetSymbolAddress((void**)&im,   g_im2col);
    cudaGetSymbolAddress((void**)&wt,   g_wt);
    cudaGetSymbolAddress((void**)&h1,   g_h1);
    cudaGetSymbolAddress((void**)&h2,   g_h2);
    cudaGetSymbolAddress((void**)&dur,  g_dur);
    cudaGetSymbolAddress((void**)&idx,  g_idx);
    cudaGetSymbolAddress((void**)&mask, g_mask);

    auto mamba = [&](const float* xin, float* xout, int L, int l,
                     const float* inw, const float* cw, const float* cb,
                     const float* xpw, const float* dtw, const float* dtb,
                     const float* alog, const float* dp, const float* ow) {
        int M = NB * L;
        launch_gemm(0, xin, inw + (size_t)l * DM * 2 * DI, xz, M, 2 * DI, DM, DM, 2 * DI, 2 * DI);
        int tot = M * DI;
        dwconv_silu_k<<<(tot + 255) / 256, 256>>>(xz, cw + (size_t)l * DI * 4, cb + (size_t)l * DI, u, L);
        launch_gemm(0, u, xpw + (size_t)l * DI * 64, xdbl, M, 64, DI, DI, 64, 64);
        launch_gemm(1, xdbl, dtw + (size_t)l * DTR * DI, delta, M, DI, DTR, 64, DI, DI,
                    dtb + (size_t)l * DI);
        scan_k<<<(NB * DI * 4 + 127) / 128, 128>>>(xdbl, delta, u, xz,
                                                   alog + (size_t)l * DI * DS,
                                                   dp + (size_t)l * DI, gate, L);
        launch_gemm(0, gate, ow + (size_t)l * DI * DM, xout, M, DM, DI, DI, DM, DM);
    };

    // embedding -> x0
    embed_k<<<(ME * DM + 255) / 256, 256>>>(text, emb, x0);

    // encoder: x0 -> x1 -> x0 -> x1 (enc_out in x1)
    mamba(x0, x1, TE, 0, enc_in_w, enc_cw, enc_cb, enc_xpw, enc_dtw, enc_dtb, enc_alog, enc_dp, enc_ow);
    mamba(x1, x0, TE, 1, enc_in_w, enc_cw, enc_cb, enc_xpw, enc_dtw, enc_dtb, enc_alog, enc_dp, enc_ow);
    mamba(x0, x1, TE, 2, enc_in_w, enc_cw, enc_cb, enc_xpw, enc_dtw, enc_dtb, enc_alog, enc_dp, enc_ow);

    // duration predictor on x1
    wt_k<<<(DM * DM * 3 + 255) / 256, 256>>>(dp_c1w, wt);
    im2col_k<<<(ME * DM * 3 + 255) / 256, 256>>>(x1, im);
    launch_gemm(2, im, wt, h1, ME, DM, 3 * DM, 3 * DM, DM, DM, dp_c1b, dp_g1, dp_b1);
    wt_k<<<(DM * DM * 3 + 255) / 256, 256>>>(dp_c2w, wt);
    im2col_k<<<(ME * DM * 3 + 255) / 256, 256>>>(h1, im);
    launch_gemm(2, im, wt, h2, ME, DM, 3 * DM, 3 * DM, DM, DM, dp_c2b, dp_g2, dp_b2);
    dur_k<<<(ME * 32 + 255) / 256, 256>>>(h2, dp_c3w, dp_c3b, dur);

    // length regulator: enc_out (x1) -> dec input (x0)
    expand_k<<<NB, TE>>>(dur, idx, mask);
    gather_k<<<(MD * DM + 255) / 256, 256>>>(x1, idx, mask, x0);

    // decoder: x0 -> x1 -> x0 -> x1
    mamba(x0, x1, TD, 0, dec_in_w, dec_cw, dec_cb, dec_xpw, dec_dtw, dec_dtb, dec_alog, dec_dpv, dec_ow);
    mamba(x1, x0, TD, 1, dec_in_w, dec_cw, dec_cb, dec_xpw, dec_dtw, dec_dtb, dec_alog, dec_dpv, dec_ow);
    mamba(x0, x1, TD, 2, dec_in_w, dec_cw, dec_cb, dec_xpw, dec_dtw, dec_dtb, dec_alog, dec_dpv, dec_ow);

    // rmsnorm -> x0, then mel projection (masked) -> d_out
    rmsnorm_k<<<MD, 128>>>(x1, norm_g, x0);
    launch_gemm(3, x0, out_w, (float*)d_out, MD, NM, DM, DM, NM, NM,
                nullptr, nullptr, nullptr, mask);

    int melN = MD * NM;  // 163840
    if (out_size > melN) {
        int n = out_size - melN;
        tail_k<<<(n + 255) / 256, 256>>>((float*)d_out + melN, mask, n);
    }
}